// round 4
// baseline (speedup 1.0000x reference)
#include <cuda_runtime.h>
#include <cuda_fp16.h>
#include <math.h>

#define N_NODES 50000
#define F_IN    50
#define H1      128
#define H2      64
#define E_MAX   1700000
#define SCAN_B  256
#define NBLK    ((N_NODES + SCAN_B - 1) / SCAN_B)   // 196

// ---- scratch (__device__ globals; no allocations allowed) ----
__device__ __align__(16) __half g_Hh[N_NODES * H1];   // h = x @ W_gcn (fp16)
__device__ int   g_deg[N_NODES];
__device__ float g_dinv[N_NODES];
__device__ int   g_rowptr[N_NODES + 1];
__device__ int   g_cursor[N_NODES];
__device__ int   g_csrc[E_MAX];
__device__ int   g_bsum[NBLK];
__device__ int   g_boff[NBLK];
__device__ float g_colsum[H1];

// ---------------------------------------------------------------------------
__global__ void k_zero() {
    int i = blockIdx.x * blockDim.x + threadIdx.x;
    if (i < N_NODES) g_deg[i] = 0;
}

// 1) in-degree histogram at dst (edge_index is int32)
__global__ void k_deg(const int* __restrict__ ei, int E) {
    int i = blockIdx.x * blockDim.x + threadIdx.x;
    if (i < E) atomicAdd(&g_deg[ei[E + i]], 1);
}

// 2a) per-block partial sums of deg
__global__ void k_scan1() {
    __shared__ int ws[8];
    int i = blockIdx.x * SCAN_B + threadIdx.x;
    int v = (i < N_NODES) ? g_deg[i] : 0;
    int lane = threadIdx.x & 31, wid = threadIdx.x >> 5;
    #pragma unroll
    for (int o = 16; o > 0; o >>= 1) v += __shfl_down_sync(0xffffffffu, v, o);
    if (lane == 0) ws[wid] = v;
    __syncthreads();
    if (threadIdx.x == 0) {
        int s = 0;
        #pragma unroll
        for (int w = 0; w < 8; w++) s += ws[w];
        g_bsum[blockIdx.x] = s;
    }
}

// 2b) single small block: exclusive scan of 196 block sums; also zero colsum
__global__ void k_scan2() {
    __shared__ int ws[8];
    int tid = threadIdx.x;           // 256 threads
    int v = (tid < NBLK) ? g_bsum[tid] : 0;
    int lane = tid & 31, wid = tid >> 5;
    int x = v;
    #pragma unroll
    for (int o = 1; o < 32; o <<= 1) {
        int y = __shfl_up_sync(0xffffffffu, x, o);
        if (lane >= o) x += y;
    }
    if (lane == 31) ws[wid] = x;
    __syncthreads();
    if (wid == 0 && lane < 8) {
        int w = ws[lane];
        #pragma unroll
        for (int o = 1; o < 8; o <<= 1) {
            int y = __shfl_up_sync(0xffu, w, o);
            if (lane >= o) w += y;
        }
        ws[lane] = w;
    }
    __syncthreads();
    int off = (wid > 0) ? ws[wid - 1] : 0;
    int excl = off + x - v;
    if (tid < NBLK) g_boff[tid] = excl;
    if (tid == NBLK - 1) g_rowptr[N_NODES] = excl + v;   // total E
    if (tid < H1) g_colsum[tid] = 0.0f;
}

// 2c) apply offsets: block-local exclusive scan + boff -> rowptr/cursor; fused dinv
__global__ void k_scan3() {
    __shared__ int ws[8];
    int i = blockIdx.x * SCAN_B + threadIdx.x;
    int v = (i < N_NODES) ? g_deg[i] : 0;
    int lane = threadIdx.x & 31, wid = threadIdx.x >> 5;
    int x = v;
    #pragma unroll
    for (int o = 1; o < 32; o <<= 1) {
        int y = __shfl_up_sync(0xffffffffu, x, o);
        if (lane >= o) x += y;
    }
    if (lane == 31) ws[wid] = x;
    __syncthreads();
    if (wid == 0 && lane < 8) {
        int w = ws[lane];
        #pragma unroll
        for (int o = 1; o < 8; o <<= 1) {
            int y = __shfl_up_sync(0xffu, w, o);
            if (lane >= o) w += y;
        }
        ws[lane] = w;
    }
    __syncthreads();
    int woff = (wid > 0) ? ws[wid - 1] : 0;
    if (i < N_NODES) {
        int p = g_boff[blockIdx.x] + woff + x - v;
        g_rowptr[i] = p;
        g_cursor[i] = p;
        g_dinv[i] = rsqrtf((float)(v + 1));
    }
}

// 3) fill CSR: group srcs by dst
__global__ void k_fill(const int* __restrict__ ei, int E) {
    int i = blockIdx.x * blockDim.x + threadIdx.x;
    if (i < E) {
        int src = ei[i];
        int dst = ei[E + i];
        int pos = atomicAdd(&g_cursor[dst], 1);
        g_csrc[pos] = src;
    }
}

// 4) h = x @ W_gcn, fp16 out. 64 threads (2 feats each), 4-node register block.
#define GN 32
__global__ void k_gemm(const float* __restrict__ x, const float* __restrict__ W) {
    __shared__ float sW[F_IN * H1];
    __shared__ float sx[GN * F_IN];
    int t = threadIdx.x;              // 0..63
    for (int i = t; i < F_IN * H1; i += 64) sW[i] = W[i];
    int node0 = blockIdx.x * GN;
    int nl = min(GN, N_NODES - node0);
    for (int i = t; i < nl * F_IN; i += 64) sx[i] = x[node0 * F_IN + i];
    __syncthreads();

    int c = 2 * t;
    __half2* Hh2 = (__half2*)g_Hh;
    for (int n = 0; n < nl; n += 4) {
        float2 a0 = {0.f, 0.f}, a1 = {0.f, 0.f}, a2 = {0.f, 0.f}, a3 = {0.f, 0.f};
        #pragma unroll
        for (int k = 0; k < F_IN; k++) {
            float w0 = sW[k * H1 + c], w1 = sW[k * H1 + c + 1];
            float x0 = sx[(n + 0) * F_IN + k];
            float x1 = sx[(n + 1) * F_IN + k];
            float x2 = sx[(n + 2) * F_IN + k];
            float x3 = sx[(n + 3) * F_IN + k];
            a0.x = fmaf(x0, w0, a0.x); a0.y = fmaf(x0, w1, a0.y);
            a1.x = fmaf(x1, w0, a1.x); a1.y = fmaf(x1, w1, a1.y);
            a2.x = fmaf(x2, w0, a2.x); a2.y = fmaf(x2, w1, a2.y);
            a3.x = fmaf(x3, w0, a3.x); a3.y = fmaf(x3, w1, a3.y);
        }
        int v = node0 + n;
        Hh2[(v + 0) * 64 + t] = __float22half2_rn(a0);
        Hh2[(v + 1) * 64 + t] = __float22half2_rn(a1);
        Hh2[(v + 2) * 64 + t] = __float22half2_rn(a2);
        Hh2[(v + 3) * 64 + t] = __float22half2_rn(a3);
    }
}

// 5) dst-centric aggregate + bias + relu + colsum. Warp-cooperative edge loads.
#define AGG_NODES 16
__global__ void k_agg(const float* __restrict__ b) {
    int t = threadIdx.x;              // 0..63, feature pair (2t, 2t+1)
    int lane = t & 31;
    int node0 = blockIdx.x * AGG_NODES;
    const __half2* __restrict__ Hh2 = (const __half2*)g_Hh;
    float bx = b[2 * t], by = b[2 * t + 1];
    float sx = 0.f, sy = 0.f;

    int nend = min(AGG_NODES, N_NODES - node0);
    for (int n = 0; n < nend; n++) {
        int v = node0 + n;
        float dv = g_dinv[v];
        float2 hv = __half22float2(Hh2[v * 64 + t]);
        float s = dv * dv;
        float ax = s * hv.x, ay = s * hv.y;

        int row = g_rowptr[v], end = g_rowptr[v + 1];
        for (int e0 = row; e0 < end; e0 += 32) {
            int m = min(32, end - e0);
            // lanes cooperatively fetch edge indices + source norms
            int   src_l  = (lane < m) ? g_csrc[e0 + lane] : 0;
            float norm_l = (lane < m) ? dv * g_dinv[src_l] : 0.f;
            #pragma unroll 4
            for (int j = 0; j < m; j++) {
                int   sj = __shfl_sync(0xffffffffu, src_l, j);
                float nj = __shfl_sync(0xffffffffu, norm_l, j);
                float2 mj = __half22float2(Hh2[sj * 64 + t]);
                ax = fmaf(nj, mj.x, ax);
                ay = fmaf(nj, mj.y, ay);
            }
        }
        sx += fmaxf(ax + bx, 0.f);
        sy += fmaxf(ay + by, 0.f);
    }
    atomicAdd(&g_colsum[2 * t], sx);
    atomicAdd(&g_colsum[2 * t + 1], sy);
}

// 6) emb = tanh( mean @ W_lin + b_lin )
__global__ void k_final(const float* __restrict__ Wl, const float* __restrict__ bl,
                        float* __restrict__ out) {
    __shared__ float mean[H1];
    int t = threadIdx.x; // 0..63
    mean[t]      = g_colsum[t]      * (1.0f / (float)N_NODES);
    mean[t + 64] = g_colsum[t + 64] * (1.0f / (float)N_NODES);
    __syncthreads();
    float acc = bl[t];
    #pragma unroll 8
    for (int k = 0; k < H1; k++)
        acc = fmaf(mean[k], Wl[k * H2 + t], acc);
    out[t] = tanhf(acc);
}

// ---------------------------------------------------------------------------
extern "C" void kernel_launch(void* const* d_in, const int* in_sizes, int n_in,
                              void* d_out, int out_size) {
    const float* x  = (const float*)d_in[0];
    const float* Wg = (const float*)d_in[1];
    const float* bg = (const float*)d_in[2];
    const float* Wl = (const float*)d_in[3];
    const float* bl = (const float*)d_in[4];
    const int*   ei = (const int*)d_in[5];
    int E = in_sizes[5] / 2;
    float* out = (float*)d_out;

    k_zero<<<NBLK, SCAN_B>>>();
    k_deg<<<(E + 255) / 256, 256>>>(ei, E);
    k_scan1<<<NBLK, SCAN_B>>>();
    k_scan2<<<1, 256>>>();
    k_scan3<<<NBLK, SCAN_B>>>();
    k_fill<<<(E + 255) / 256, 256>>>(ei, E);
    k_gemm<<<(N_NODES + GN - 1) / GN, 64>>>(x, Wg);
    k_agg<<<(N_NODES + AGG_NODES - 1) / AGG_NODES, 64>>>(bg);
    k_final<<<1, H2>>>(Wl, bl, out);
}

// round 5
// speedup vs baseline: 1.0821x; 1.0821x over previous
#include <cuda_runtime.h>
#include <cuda_fp16.h>
#include <math.h>

#define N_NODES 50000
#define F_IN    50
#define H1      128
#define H2      64
#define E_MAX   1700000

// ---- scratch (__device__ globals; no allocations allowed) ----
__device__ __align__(16) __half g_Hh[N_NODES * H1];   // h = x @ W_gcn (fp16)
__device__ int   g_deg[N_NODES];
__device__ float g_dinv[N_NODES];
__device__ int   g_rowptr[N_NODES + 1];
__device__ int   g_cursor[N_NODES];
__device__ int   g_csrc[E_MAX];
__device__ float g_colsum[H1];

// ---------------------------------------------------------------------------
// 0) zero deg + colsum
__global__ void k_zero() {
    int i = blockIdx.x * blockDim.x + threadIdx.x;
    if (i < N_NODES) g_deg[i] = 0;
    if (i < H1) g_colsum[i] = 0.0f;
}

// 1) in-degree histogram at dst (edge_index is int32)
__global__ void k_deg(const int* __restrict__ ei, int E) {
    int i = blockIdx.x * blockDim.x + threadIdx.x;
    if (i < E) atomicAdd(&g_deg[ei[E + i]], 1);
}

// 2) single-block serial-chunk scan over deg -> rowptr/cursor, fused dinv
__global__ void k_scan() {
    __shared__ int warp_sums[32];
    __shared__ int s_carry;
    int tid = threadIdx.x, lane = tid & 31, wid = tid >> 5;
    if (tid == 0) s_carry = 0;
    __syncthreads();
    for (int base = 0; base < N_NODES; base += 1024) {
        int i = base + tid;
        int v = (i < N_NODES) ? g_deg[i] : 0;
        int x = v;
        #pragma unroll
        for (int o = 1; o < 32; o <<= 1) {
            int y = __shfl_up_sync(0xffffffffu, x, o);
            if (lane >= o) x += y;
        }
        if (lane == 31) warp_sums[wid] = x;
        __syncthreads();
        if (wid == 0) {
            int w = warp_sums[lane];
            #pragma unroll
            for (int o = 1; o < 32; o <<= 1) {
                int y = __shfl_up_sync(0xffffffffu, w, o);
                if (lane >= o) w += y;
            }
            warp_sums[lane] = w;
        }
        __syncthreads();
        int warp_off = (wid > 0) ? warp_sums[wid - 1] : 0;
        int excl = x + warp_off - v;
        int carry = s_carry;
        if (i < N_NODES) {
            int p = carry + excl;
            g_rowptr[i] = p;
            g_cursor[i] = p;
            g_dinv[i] = rsqrtf((float)(v + 1));
        }
        int total = warp_sums[31];
        __syncthreads();
        if (tid == 0) s_carry = carry + total;
        __syncthreads();
    }
    if (threadIdx.x == 0) g_rowptr[N_NODES] = s_carry;
}

// 3) fill CSR: group srcs by dst
__global__ void k_fill(const int* __restrict__ ei, int E) {
    int i = blockIdx.x * blockDim.x + threadIdx.x;
    if (i < E) {
        int src = ei[i];
        int dst = ei[E + i];
        int pos = atomicAdd(&g_cursor[dst], 1);
        g_csrc[pos] = src;
    }
}

// 4) h = x @ W_gcn, fp16 out. 64 threads (2 feats each), 4-node register block.
#define GN 32
__global__ void k_gemm(const float* __restrict__ x, const float* __restrict__ W) {
    __shared__ float sW[F_IN * H1];
    __shared__ float sx[GN * F_IN];
    int t = threadIdx.x;              // 0..63
    for (int i = t; i < F_IN * H1; i += 64) sW[i] = W[i];
    int node0 = blockIdx.x * GN;
    int nl = min(GN, N_NODES - node0);
    for (int i = t; i < nl * F_IN; i += 64) sx[i] = x[node0 * F_IN + i];
    __syncthreads();

    int c = 2 * t;
    __half2* Hh2 = (__half2*)g_Hh;
    for (int n = 0; n < nl; n += 4) {
        float2 a0 = {0.f, 0.f}, a1 = {0.f, 0.f}, a2 = {0.f, 0.f}, a3 = {0.f, 0.f};
        #pragma unroll
        for (int k = 0; k < F_IN; k++) {
            float w0 = sW[k * H1 + c], w1 = sW[k * H1 + c + 1];
            float x0 = sx[(n + 0) * F_IN + k];
            float x1 = sx[(n + 1) * F_IN + k];
            float x2 = sx[(n + 2) * F_IN + k];
            float x3 = sx[(n + 3) * F_IN + k];
            a0.x = fmaf(x0, w0, a0.x); a0.y = fmaf(x0, w1, a0.y);
            a1.x = fmaf(x1, w0, a1.x); a1.y = fmaf(x1, w1, a1.y);
            a2.x = fmaf(x2, w0, a2.x); a2.y = fmaf(x2, w1, a2.y);
            a3.x = fmaf(x3, w0, a3.x); a3.y = fmaf(x3, w1, a3.y);
        }
        int v = node0 + n;
        Hh2[(v + 0) * 64 + t] = __float22half2_rn(a0);
        Hh2[(v + 1) * 64 + t] = __float22half2_rn(a1);
        Hh2[(v + 2) * 64 + t] = __float22half2_rn(a2);
        Hh2[(v + 3) * 64 + t] = __float22half2_rn(a3);
    }
}

// 5) dst-centric aggregate + bias + relu + colsum. Broadcast index loads, 4x unroll.
#define AGG_NODES 16
__global__ void k_agg(const float* __restrict__ b) {
    int t = threadIdx.x;              // 0..63, feature pair (2t, 2t+1)
    int node0 = blockIdx.x * AGG_NODES;
    const __half2* __restrict__ Hh2 = (const __half2*)g_Hh;
    float bx = b[2 * t], by = b[2 * t + 1];
    float sx = 0.f, sy = 0.f;

    int nend = min(AGG_NODES, N_NODES - node0);
    for (int n = 0; n < nend; n++) {
        int v = node0 + n;
        float dv = g_dinv[v];
        float2 hv = __half22float2(Hh2[v * 64 + t]);
        float s = dv * dv;
        float ax = s * hv.x, ay = s * hv.y;

        int e = g_rowptr[v], end = g_rowptr[v + 1];
        for (; e + 3 < end; e += 4) {
            int s0 = g_csrc[e],     s1 = g_csrc[e + 1];
            int s2 = g_csrc[e + 2], s3 = g_csrc[e + 3];
            float n0 = dv * g_dinv[s0];
            float n1 = dv * g_dinv[s1];
            float n2 = dv * g_dinv[s2];
            float n3 = dv * g_dinv[s3];
            float2 m0 = __half22float2(Hh2[s0 * 64 + t]);
            float2 m1 = __half22float2(Hh2[s1 * 64 + t]);
            float2 m2 = __half22float2(Hh2[s2 * 64 + t]);
            float2 m3 = __half22float2(Hh2[s3 * 64 + t]);
            ax = fmaf(n0, m0.x, ax); ay = fmaf(n0, m0.y, ay);
            ax = fmaf(n1, m1.x, ax); ay = fmaf(n1, m1.y, ay);
            ax = fmaf(n2, m2.x, ax); ay = fmaf(n2, m2.y, ay);
            ax = fmaf(n3, m3.x, ax); ay = fmaf(n3, m3.y, ay);
        }
        for (; e < end; e++) {
            int s0 = g_csrc[e];
            float n0 = dv * g_dinv[s0];
            float2 m0 = __half22float2(Hh2[s0 * 64 + t]);
            ax = fmaf(n0, m0.x, ax); ay = fmaf(n0, m0.y, ay);
        }
        sx += fmaxf(ax + bx, 0.f);
        sy += fmaxf(ay + by, 0.f);
    }
    atomicAdd(&g_colsum[2 * t], sx);
    atomicAdd(&g_colsum[2 * t + 1], sy);
}

// 6) emb = tanh( mean @ W_lin + b_lin )
__global__ void k_final(const float* __restrict__ Wl, const float* __restrict__ bl,
                        float* __restrict__ out) {
    __shared__ float mean[H1];
    int t = threadIdx.x; // 0..63
    mean[t]      = g_colsum[t]      * (1.0f / (float)N_NODES);
    mean[t + 64] = g_colsum[t + 64] * (1.0f / (float)N_NODES);
    __syncthreads();
    float acc = bl[t];
    #pragma unroll 8
    for (int k = 0; k < H1; k++)
        acc = fmaf(mean[k], Wl[k * H2 + t], acc);
    out[t] = tanhf(acc);
}

// ---------------------------------------------------------------------------
extern "C" void kernel_launch(void* const* d_in, const int* in_sizes, int n_in,
                              void* d_out, int out_size) {
    const float* x  = (const float*)d_in[0];
    const float* Wg = (const float*)d_in[1];
    const float* bg = (const float*)d_in[2];
    const float* Wl = (const float*)d_in[3];
    const float* bl = (const float*)d_in[4];
    const int*   ei = (const int*)d_in[5];
    int E = in_sizes[5] / 2;
    float* out = (float*)d_out;

    // one-time host-side infra (created on the first, non-capturing call;
    // identical device work on every call)
    static cudaStream_t s_side = nullptr;
    static cudaEvent_t  s_ev_fork = nullptr, s_ev_join = nullptr;
    if (s_side == nullptr) {
        cudaStreamCreateWithFlags(&s_side, cudaStreamNonBlocking);
        cudaEventCreateWithFlags(&s_ev_fork, cudaEventDisableTiming);
        cudaEventCreateWithFlags(&s_ev_join, cudaEventDisableTiming);
    }

    // fork: gemm (depends only on x, W) runs concurrently with CSR build
    cudaEventRecord(s_ev_fork, 0);
    cudaStreamWaitEvent(s_side, s_ev_fork, 0);
    k_gemm<<<(N_NODES + GN - 1) / GN, 64, 0, s_side>>>(x, Wg);
    cudaEventRecord(s_ev_join, s_side);

    // CSR build chain on the main (capture) stream
    k_zero<<<(N_NODES + 1023) / 1024, 1024>>>();
    k_deg<<<(E + 255) / 256, 256>>>(ei, E);
    k_scan<<<1, 1024>>>();
    k_fill<<<(E + 255) / 256, 256>>>(ei, E);

    // join: agg needs both h (gemm) and CSR
    cudaStreamWaitEvent(0, s_ev_join, 0);
    k_agg<<<(N_NODES + AGG_NODES - 1) / AGG_NODES, 64>>>(bg);
    k_final<<<1, H2>>>(Wl, bl, out);
}

// round 7
// speedup vs baseline: 1.3079x; 1.2087x over previous
#include <cuda_runtime.h>
#include <cuda_fp16.h>
#include <math.h>

#define N_NODES 50000
#define F_IN    50
#define H1      128
#define H2      64
#define E_MAX   1700000
#define SCAN_B  256
#define NBLK    ((N_NODES + SCAN_B - 1) / SCAN_B)   // 196

// ---- scratch (__device__ globals; no allocations allowed) ----
__device__ __align__(16) __half g_Hh[N_NODES * H1];   // h = x @ W_gcn (fp16)
__device__ int   g_deg[N_NODES];                      // zeroed at end of k_scan3
__device__ float g_dinv[N_NODES];
__device__ int   g_rowptr[N_NODES + 1];
__device__ int   g_cursor[N_NODES];
__device__ int   g_csrc[E_MAX];
__device__ int   g_bsum[NBLK];
__device__ int   g_boff[NBLK];
__device__ float g_colsum[H1];                        // zeroed at end of k_final

// ---------------------------------------------------------------------------
// 1) in-degree histogram at dst (edge_index is int32; g_deg pre-zeroed)
__global__ void k_deg(const int* __restrict__ ei, int E) {
    int i = blockIdx.x * blockDim.x + threadIdx.x;
    if (i < E) atomicAdd(&g_deg[ei[E + i]], 1);
}

// 2a) per-block partial sums of deg
__global__ void k_scan1() {
    __shared__ int ws[8];
    int i = blockIdx.x * SCAN_B + threadIdx.x;
    int v = (i < N_NODES) ? g_deg[i] : 0;
    int lane = threadIdx.x & 31, wid = threadIdx.x >> 5;
    #pragma unroll
    for (int o = 16; o > 0; o >>= 1) v += __shfl_down_sync(0xffffffffu, v, o);
    if (lane == 0) ws[wid] = v;
    __syncthreads();
    if (threadIdx.x == 0) {
        int s = 0;
        #pragma unroll
        for (int w = 0; w < 8; w++) s += ws[w];
        g_bsum[blockIdx.x] = s;
    }
}

// 2b) one small block: exclusive scan of the 196 block sums
__global__ void k_scan2() {
    __shared__ int ws[8];
    int tid = threadIdx.x;           // 256 threads
    int v = (tid < NBLK) ? g_bsum[tid] : 0;
    int lane = tid & 31, wid = tid >> 5;
    int x = v;
    #pragma unroll
    for (int o = 1; o < 32; o <<= 1) {
        int y = __shfl_up_sync(0xffffffffu, x, o);
        if (lane >= o) x += y;
    }
    if (lane == 31) ws[wid] = x;
    __syncthreads();
    if (wid == 0 && lane < 8) {
        int w = ws[lane];
        #pragma unroll
        for (int o = 1; o < 8; o <<= 1) {
            int y = __shfl_up_sync(0xffu, w, o);
            if (lane >= o) w += y;
        }
        ws[lane] = w;
    }
    __syncthreads();
    int off = (wid > 0) ? ws[wid - 1] : 0;
    int excl = off + x - v;
    if (tid < NBLK) g_boff[tid] = excl;
    if (tid == NBLK - 1) g_rowptr[N_NODES] = excl + v;
}

// 2c) apply offsets -> rowptr/cursor; fused dinv; re-zero deg for next replay
__global__ void k_scan3() {
    __shared__ int ws[8];
    int i = blockIdx.x * SCAN_B + threadIdx.x;
    int v = (i < N_NODES) ? g_deg[i] : 0;
    int lane = threadIdx.x & 31, wid = threadIdx.x >> 5;
    int x = v;
    #pragma unroll
    for (int o = 1; o < 32; o <<= 1) {
        int y = __shfl_up_sync(0xffffffffu, x, o);
        if (lane >= o) x += y;
    }
    if (lane == 31) ws[wid] = x;
    __syncthreads();
    if (wid == 0 && lane < 8) {
        int w = ws[lane];
        #pragma unroll
        for (int o = 1; o < 8; o <<= 1) {
            int y = __shfl_up_sync(0xffu, w, o);
            if (lane >= o) w += y;
        }
        ws[lane] = w;
    }
    __syncthreads();
    int woff = (wid > 0) ? ws[wid - 1] : 0;
    if (i < N_NODES) {
        int p = g_boff[blockIdx.x] + woff + x - v;
        g_rowptr[i] = p;
        g_cursor[i] = p;
        g_dinv[i] = rsqrtf((float)(v + 1));
        g_deg[i] = 0;                 // ready for next call
    }
}

// 3) fill CSR: group srcs by dst
__global__ void k_fill(const int* __restrict__ ei, int E) {
    int i = blockIdx.x * blockDim.x + threadIdx.x;
    if (i < E) {
        int src = ei[i];
        int dst = ei[E + i];
        int pos = atomicAdd(&g_cursor[dst], 1);
        g_csrc[pos] = src;
    }
}

// 4) h = x @ W_gcn, fp16 out. 64 threads (2 feats each), 4-node register block.
#define GN 32
__global__ void k_gemm(const float* __restrict__ x, const float* __restrict__ W) {
    __shared__ float sW[F_IN * H1];
    __shared__ float sx[GN * F_IN];
    int t = threadIdx.x;              // 0..63
    for (int i = t; i < F_IN * H1; i += 64) sW[i] = W[i];
    int node0 = blockIdx.x * GN;
    int nl = min(GN, N_NODES - node0);
    for (int i = t; i < nl * F_IN; i += 64) sx[i] = x[node0 * F_IN + i];
    __syncthreads();

    int c = 2 * t;
    __half2* Hh2 = (__half2*)g_Hh;
    for (int n = 0; n < nl; n += 4) {
        float2 a0 = {0.f, 0.f}, a1 = {0.f, 0.f}, a2 = {0.f, 0.f}, a3 = {0.f, 0.f};
        #pragma unroll
        for (int k = 0; k < F_IN; k++) {
            float w0 = sW[k * H1 + c], w1 = sW[k * H1 + c + 1];
            float x0 = sx[(n + 0) * F_IN + k];
            float x1 = sx[(n + 1) * F_IN + k];
            float x2 = sx[(n + 2) * F_IN + k];
            float x3 = sx[(n + 3) * F_IN + k];
            a0.x = fmaf(x0, w0, a0.x); a0.y = fmaf(x0, w1, a0.y);
            a1.x = fmaf(x1, w0, a1.x); a1.y = fmaf(x1, w1, a1.y);
            a2.x = fmaf(x2, w0, a2.x); a2.y = fmaf(x2, w1, a2.y);
            a3.x = fmaf(x3, w0, a3.x); a3.y = fmaf(x3, w1, a3.y);
        }
        int v = node0 + n;
        Hh2[(v + 0) * 64 + t] = __float22half2_rn(a0);
        Hh2[(v + 1) * 64 + t] = __float22half2_rn(a1);
        Hh2[(v + 2) * 64 + t] = __float22half2_rn(a2);
        Hh2[(v + 3) * 64 + t] = __float22half2_rn(a3);
    }
}

// 5) dst-centric aggregate + bias + relu + colsum. Broadcast index loads, 4x unroll.
#define AGG_NODES 16
__global__ void k_agg(const float* __restrict__ b) {
    int t = threadIdx.x;              // 0..63, feature pair (2t, 2t+1)
    int node0 = blockIdx.x * AGG_NODES;
    const __half2* __restrict__ Hh2 = (const __half2*)g_Hh;
    float bx = b[2 * t], by = b[2 * t + 1];
    float sx = 0.f, sy = 0.f;

    int nend = min(AGG_NODES, N_NODES - node0);
    for (int n = 0; n < nend; n++) {
        int v = node0 + n;
        float dv = g_dinv[v];
        float2 hv = __half22float2(Hh2[v * 64 + t]);
        float s = dv * dv;
        float ax = s * hv.x, ay = s * hv.y;

        int e = g_rowptr[v], end = g_rowptr[v + 1];
        for (; e + 3 < end; e += 4) {
            int s0 = g_csrc[e],     s1 = g_csrc[e + 1];
            int s2 = g_csrc[e + 2], s3 = g_csrc[e + 3];
            float n0 = dv * g_dinv[s0];
            float n1 = dv * g_dinv[s1];
            float n2 = dv * g_dinv[s2];
            float n3 = dv * g_dinv[s3];
            float2 m0 = __half22float2(Hh2[s0 * 64 + t]);
            float2 m1 = __half22float2(Hh2[s1 * 64 + t]);
            float2 m2 = __half22float2(Hh2[s2 * 64 + t]);
            float2 m3 = __half22float2(Hh2[s3 * 64 + t]);
            ax = fmaf(n0, m0.x, ax); ay = fmaf(n0, m0.y, ay);
            ax = fmaf(n1, m1.x, ax); ay = fmaf(n1, m1.y, ay);
            ax = fmaf(n2, m2.x, ax); ay = fmaf(n2, m2.y, ay);
            ax = fmaf(n3, m3.x, ax); ay = fmaf(n3, m3.y, ay);
        }
        for (; e < end; e++) {
            int s0 = g_csrc[e];
            float n0 = dv * g_dinv[s0];
            float2 m0 = __half22float2(Hh2[s0 * 64 + t]);
            ax = fmaf(n0, m0.x, ax); ay = fmaf(n0, m0.y, ay);
        }
        sx += fmaxf(ax + bx, 0.f);
        sy += fmaxf(ay + by, 0.f);
    }
    atomicAdd(&g_colsum[2 * t], sx);
    atomicAdd(&g_colsum[2 * t + 1], sy);
}

// 6) emb = tanh( mean @ W_lin + b_lin ); re-zero colsum for next replay
__global__ void k_final(const float* __restrict__ Wl, const float* __restrict__ bl,
                        float* __restrict__ out) {
    __shared__ float mean[H1];
    int t = threadIdx.x; // 0..63
    mean[t]      = g_colsum[t]      * (1.0f / (float)N_NODES);
    mean[t + 64] = g_colsum[t + 64] * (1.0f / (float)N_NODES);
    g_colsum[t] = 0.0f;
    g_colsum[t + 64] = 0.0f;
    __syncthreads();
    float acc = bl[t];
    #pragma unroll 8
    for (int k = 0; k < H1; k++)
        acc = fmaf(mean[k], Wl[k * H2 + t], acc);
    out[t] = tanhf(acc);
}

// ---------------------------------------------------------------------------
extern "C" void kernel_launch(void* const* d_in, const int* in_sizes, int n_in,
                              void* d_out, int out_size) {
    const float* x  = (const float*)d_in[0];
    const float* Wg = (const float*)d_in[1];
    const float* bg = (const float*)d_in[2];
    const float* Wl = (const float*)d_in[3];
    const float* bl = (const float*)d_in[4];
    const int*   ei = (const int*)d_in[5];
    int E = in_sizes[5] / 2;
    float* out = (float*)d_out;

    // one-time host-side infra (outside capture on first call)
    static cudaStream_t s_side = nullptr;
    static cudaEvent_t  s_ev_fork = nullptr, s_ev_join = nullptr;
    if (s_side == nullptr) {
        cudaStreamCreateWithFlags(&s_side, cudaStreamNonBlocking);
        cudaEventCreateWithFlags(&s_ev_fork, cudaEventDisableTiming);
        cudaEventCreateWithFlags(&s_ev_join, cudaEventDisableTiming);
    }

    // fork: gemm (depends only on x, W) overlaps the CSR build
    cudaEventRecord(s_ev_fork, 0);
    cudaStreamWaitEvent(s_side, s_ev_fork, 0);
    k_gemm<<<(N_NODES + GN - 1) / GN, 64, 0, s_side>>>(x, Wg);
    cudaEventRecord(s_ev_join, s_side);

    // CSR build chain on the main (capture) stream
    k_deg<<<(E + 255) / 256, 256>>>(ei, E);
    k_scan1<<<NBLK, SCAN_B>>>();
    k_scan2<<<1, 256>>>();
    k_scan3<<<NBLK, SCAN_B>>>();
    k_fill<<<(E + 255) / 256, 256>>>(ei, E);

    // join: agg needs both h (gemm) and CSR
    cudaStreamWaitEvent(0, s_ev_join, 0);
    k_agg<<<(N_NODES + AGG_NODES - 1) / AGG_NODES, 64>>>(bg);
    k_final<<<1, H2>>>(Wl, bl, out);
}